// round 13
// baseline (speedup 1.0000x reference)
#include <cuda_runtime.h>
#include <cstdint>

#define Bn   8
#define Sn   4096
#define Dm   512
#define Fn   2049
#define Em   8
#define DFF  2048
#define NT   (Bn * Fn)      /* 16392 tokens in frequency domain */
#define NSLOT (2 * NT)      /* 32784 token-expert slots */

/* ---------------- scratch (device globals; no runtime alloc allowed) -------- */
__device__ float g_xfri[16785408];   /* NT x 1024  (re | im), EXACT fp32 */
__device__ float g_h   [8392704];    /* NT x 512  (tf32-rounded at pin epi) */
__device__ float g_moe [8392704];    /* NT x 512  (tf32-rounded at combine) */
__device__ float g_of  [16785408];   /* NT x 1024 */
__device__ float g_ot  [16777216];   /* B x S x D */
__device__ float g_hid [67141632];   /* NSLOT x 2048 (tf32-rounded at store) */
__device__ float g_eout[16785408];   /* NSLOT x 512 */
__device__ float g_w1t [8388608];    /* tf32-rounded w1 */
__device__ float g_w2t [8388608];    /* tf32-rounded w2 */
__device__ float g_poutt[524288];    /* tf32-rounded pout_w */
__device__ float g_pint [524288];    /* tf32-rounded pin_w */
__device__ float g_wr  [8192];       /* fused router weights pin_w @ router_w */
__device__ float g_br  [8];          /* fused router bias */
__device__ float2 g_tw [4096];       /* twiddle table: index = half + pos */
__device__ int   g_top_idx[NT * 2];
__device__ float g_top_w [NT * 2];
__device__ int   g_counts[Em];
__device__ int   g_offsets[Em];
__device__ int   g_cursor[Em];
__device__ int   g_slot_token[NSLOT];
__device__ int   g_tok_slot[NT * 2];

__device__ __forceinline__ unsigned f2tf(float f) {
    unsigned u;
    asm("cvt.rna.tf32.f32 %0, %1;" : "=r"(u) : "f"(f));
    return u;
}

/* ---------------- setup: zero counts + build twiddle table ---------------- */
__global__ void setup_kernel() {
    int i = blockIdx.x * blockDim.x + threadIdx.x;
    if (i < Em) g_counts[i] = 0;
    if (i >= 1 && i < 4096) {
        int half = 1 << (31 - __clz(i));
        int pos  = i - half;
        float ang = -6.283185307179586f * (float)pos / (float)(2 * half);
        float sn, cs;
        sincosf(ang, &sn, &cs);
        g_tw[i] = make_float2(cs, sn);
    }
}

/* ---------------- pre-round weights to tf32 (once per launch) ------------- */
__global__ void preround_kernel(const float* __restrict__ w1,
                                const float* __restrict__ w2,
                                const float* __restrict__ pw,
                                const float* __restrict__ piw) {
    int i = blockIdx.x * blockDim.x + threadIdx.x;
    if (i < 8388608) {
        g_w1t[i] = __uint_as_float(f2tf(w1[i]));
        g_w2t[i] = __uint_as_float(f2tf(w2[i]));
    }
    if (i < 524288) {
        g_poutt[i] = __uint_as_float(f2tf(pw[i]));
        g_pint[i]  = __uint_as_float(f2tf(piw[i]));
    }
}

/* ---------------- fused router weights: Wr = pin_w @ router_w ------------- */
__global__ void wr_kernel(const float* __restrict__ pin_w,
                          const float* __restrict__ pin_b,
                          const float* __restrict__ rw,
                          const float* __restrict__ rb) {
    int f = blockIdx.x, tid = threadIdx.x;
    if (f == 1024) {
        if (tid < 8) {
            float s = rb[tid];
            for (int d = 0; d < 512; d++) s += pin_b[d] * rw[d * 8 + tid];
            g_br[tid] = s;
        }
        return;
    }
    float acc[8] = {0.f, 0.f, 0.f, 0.f, 0.f, 0.f, 0.f, 0.f};
    for (int d = tid; d < 512; d += 128) {
        float pv = pin_w[f * 512 + d];
        const float* r = rw + d * 8;
#pragma unroll
        for (int e = 0; e < 8; e++) acc[e] += pv * r[e];
    }
    __shared__ float red[4][8];
#pragma unroll
    for (int e = 0; e < 8; e++)
        for (int o = 16; o; o >>= 1)
            acc[e] += __shfl_down_sync(0xffffffffu, acc[e], o);
    if ((tid & 31) == 0) {
#pragma unroll
        for (int e = 0; e < 8; e++) red[tid >> 5][e] = acc[e];
    }
    __syncthreads();
    if (tid < 8)
        g_wr[f * 8 + tid] = red[0][tid] + red[1][tid] + red[2][tid] + red[3][tid];
}

/* skewed smem index: kills 2-way bank conflicts in butterfly stages */
#define IX(i) ((i) + ((i) >> 5))

/* base-4 digit reversal of a 12-bit index */
__device__ __forceinline__ unsigned dr4(unsigned s) {
    unsigned t = __brev(s) >> 20;
    return ((t & 0x555u) << 1) | ((t >> 1) & 0x555u);
}

template <int INV, int S>
__device__ __forceinline__ void bfly4(float* xr, float* xi,
                                      float2 w1, float2 w2) {
    float w1i = INV ? -w1.y : w1.y;
    float w2i = INV ? -w2.y : w2.y;
    float w3r = w1.x * w2.x - w1i * w2i;
    float w3i = w1.x * w2i + w1i * w2.x;
    float t0r = xr[0], t0i = xi[0];
    float t1r = xr[S] * w1.x - xi[S] * w1i;
    float t1i = xr[S] * w1i + xi[S] * w1.x;
    float t2r = xr[2 * S] * w2.x - xi[2 * S] * w2i;
    float t2i = xr[2 * S] * w2i + xi[2 * S] * w2.x;
    float t3r = xr[3 * S] * w3r - xi[3 * S] * w3i;
    float t3i = xr[3 * S] * w3i + xi[3 * S] * w3r;
    float s0r = t0r + t2r, s0i = t0i + t2i;
    float s1r = t0r - t2r, s1i = t0i - t2i;
    float s2r = t1r + t3r, s2i = t1i + t3i;
    float s3r = t1r - t3r, s3i = t1i - t3i;
    xr[0] = s0r + s2r;     xi[0] = s0i + s2i;
    xr[2 * S] = s0r - s2r; xi[2 * S] = s0i - s2i;
    if (!INV) {
        xr[S] = s1r + s3i;     xi[S] = s1i - s3r;
        xr[3 * S] = s1r - s3i; xi[3 * S] = s1i + s3r;
    } else {
        xr[S] = s1r - s3i;     xi[S] = s1i + s3r;
        xr[3 * S] = s1r + s3i; xi[3 * S] = s1i - s3r;
    }
}

template <int INV>
__device__ __forceinline__ void pair16(float* xr, float* xi, int Q, int pos) {
    float2 wA1 = g_tw[2 * Q + pos];
    float2 wA2 = g_tw[Q + pos];
#pragma unroll
    for (int b = 0; b < 4; b++)
        bfly4<INV, 1>(xr + 4 * b, xi + 4 * b, wA1, wA2);
#pragma unroll
    for (int c = 0; c < 4; c++) {
        float2 wB1 = g_tw[8 * Q + pos + c * Q];
        float2 wB2 = g_tw[4 * Q + pos + c * Q];
        bfly4<INV, 4>(xr + c, xi + c, wB1, wB2);
    }
}

/* ---------------- forward rfft, two d-columns per block (two-for-one) ------ */
__global__ __launch_bounds__(256) void fft_fwd_kernel(const float* __restrict__ x) {
    __shared__ float re[4224];
    __shared__ float im[4224];
    int pr = blockIdx.x;
    int b = pr >> 8, d0 = (pr & 255) << 1;
    int tid = threadIdx.x;

    float xr[16], xi[16];

#pragma unroll
    for (int k = 0; k < 16; k++) {
        unsigned s = dr4((unsigned)(16 * tid + k));
        float2 v = *(const float2*)(x + ((size_t)b * Sn + s) * Dm + d0);
        xr[k] = v.x;
        xi[k] = v.y;
    }
    pair16<0>(xr, xi, 1, 0);
#pragma unroll
    for (int k = 0; k < 16; k++) {
        int i = 16 * tid + k;
        re[IX(i)] = xr[k];
        im[IX(i)] = xi[k];
    }
    __syncthreads();

    {
        int pos = tid & 15, g = ((tid >> 4) << 8) + pos;
#pragma unroll
        for (int k = 0; k < 16; k++) {
            int i = g + (k << 4);
            xr[k] = re[IX(i)];
            xi[k] = im[IX(i)];
        }
        pair16<0>(xr, xi, 16, pos);
#pragma unroll
        for (int k = 0; k < 16; k++) {
            int i = g + (k << 4);
            re[IX(i)] = xr[k];
            im[IX(i)] = xi[k];
        }
    }
    __syncthreads();

    {
#pragma unroll
        for (int k = 0; k < 16; k++) {
            int i = tid + (k << 8);
            xr[k] = re[IX(i)];
            xi[k] = im[IX(i)];
        }
        pair16<0>(xr, xi, 256, tid);
#pragma unroll
        for (int k = 0; k < 16; k++) {
            int i = tid + (k << 8);
            re[IX(i)] = xr[k];
            im[IX(i)] = xi[k];
        }
    }
    __syncthreads();

    const float sc = 0.5f * 0.015625f;   /* 0.5 (split) * 1/sqrt(4096) */
    for (int k = tid; k <= 2048; k += 256) {
        int k2 = (4096 - k) & 4095;
        float zr  = re[IX(k)],  zi  = im[IX(k)];
        float z2r = re[IX(k2)], z2i = im[IX(k2)];
        float xdr = (zr + z2r) * sc, xdi = (zi - z2i) * sc;
        float xer = (zi + z2i) * sc, xei = (z2r - zr) * sc;
        size_t o = ((size_t)b * Fn + k) * 1024 + d0;
        *(float2*)(g_xfri + o)       = make_float2(xdr, xer);
        *(float2*)(g_xfri + o + 512) = make_float2(xdi, xei);
    }
}

/* ---------------- inverse rfft, two d-columns per block -------------------- */
__global__ __launch_bounds__(256) void fft_inv_kernel() {
    __shared__ float re[4224];
    __shared__ float im[4224];
    int pr = blockIdx.x;
    int b = pr >> 8, d0 = (pr & 255) << 1;
    int tid = threadIdx.x;

    float xr[16], xi[16];

#pragma unroll
    for (int k = 0; k < 16; k++) {
        unsigned ks = dr4((unsigned)(16 * tid + k));
        float zr, zi;
        if (ks <= 2048) {
            size_t o = ((size_t)b * Fn + ks) * 1024 + d0;
            float2 vre = *(const float2*)(g_of + o);
            float2 vim = *(const float2*)(g_of + o + 512);
            float a = vre.x, c = vre.y, bb = vim.x, dd = vim.y;
            if (ks == 0 || ks == 2048) { bb = 0.f; dd = 0.f; }
            zr = a - dd;
            zi = bb + c;
        } else {
            int k2 = 4096 - (int)ks;
            size_t o = ((size_t)b * Fn + k2) * 1024 + d0;
            float2 vre = *(const float2*)(g_of + o);
            float2 vim = *(const float2*)(g_of + o + 512);
            float a = vre.x, c = vre.y, bb = vim.x, dd = vim.y;
            zr = a + dd;
            zi = c - bb;
        }
        xr[k] = zr;
        xi[k] = zi;
    }
    pair16<1>(xr, xi, 1, 0);
#pragma unroll
    for (int k = 0; k < 16; k++) {
        int i = 16 * tid + k;
        re[IX(i)] = xr[k];
        im[IX(i)] = xi[k];
    }
    __syncthreads();

    {
        int pos = tid & 15, g = ((tid >> 4) << 8) + pos;
#pragma unroll
        for (int k = 0; k < 16; k++) {
            int i = g + (k << 4);
            xr[k] = re[IX(i)];
            xi[k] = im[IX(i)];
        }
        pair16<1>(xr, xi, 16, pos);
#pragma unroll
        for (int k = 0; k < 16; k++) {
            int i = g + (k << 4);
            re[IX(i)] = xr[k];
            im[IX(i)] = xi[k];
        }
    }
    __syncthreads();

    {
#pragma unroll
        for (int k = 0; k < 16; k++) {
            int i = tid + (k << 8);
            xr[k] = re[IX(i)];
            xi[k] = im[IX(i)];
        }
        pair16<1>(xr, xi, 256, tid);
        const float sc = 0.015625f;
#pragma unroll
        for (int k = 0; k < 16; k++) {
            int s = tid + (k << 8);
            *(float2*)(g_ot + ((size_t)b * Sn + s) * Dm + d0) =
                make_float2(xr[k] * sc, xi[k] * sc);
        }
    }
}

/* ==================== pipelined tf32 tensor-core GEMM ====================
   Block tile 128(M) x 128(N) x 32(K), 256 threads = 8 warps (2x4).
   Warp tile 64x32 = 4x4 grid of mma.sync.m16n8k8 tf32 tiles.
   4-stage cp.async pipeline (128KB dynamic smem), ONE __syncthreads per
   K-iteration: load target buffer (it+3)&3 was last read at iteration it-1,
   so the top-of-loop barrier alone orders reuse.
   MODE 0: g_h   = cvt(g_xfri) @ g_pint + pin_b          (K=1024, N=512)
   MODE 1: g_of  = g_moe  @ g_poutt + pout_b             (K=512,  N=1024)
   MODE 2: g_hid = gelu(gather(g_h) @ g_w1t + b1[e])     (K=512,  N=2048)
   MODE 3: g_eout= g_hid @ g_w2t + b2[e]                 (K=2048, N=512)  */

__device__ __forceinline__ void mma_tf32(float c[4], const unsigned a[4],
                                         const unsigned b[2]) {
    asm volatile(
        "mma.sync.aligned.m16n8k8.row.col.f32.tf32.tf32.f32 "
        "{%0,%1,%2,%3}, {%4,%5,%6,%7}, {%8,%9}, {%0,%1,%2,%3};\n"
        : "+f"(c[0]), "+f"(c[1]), "+f"(c[2]), "+f"(c[3])
        : "r"(a[0]), "r"(a[1]), "r"(a[2]), "r"(a[3]), "r"(b[0]), "r"(b[1]));
}

/* dynamic smem layout (floats):
   As[4][128][32] at 0      (stage s at s*4096)
   Bs[4][32][128] at 16384  (stage s at 16384 + s*4096)                    */
template <int MODE>
__global__ __launch_bounds__(256) void gemm_tf32_kernel(
        const float* __restrict__ bias) {
    constexpr int K = (MODE == 0) ? 1024 : (MODE == 3) ? 2048 : 512;
    constexpr int N = (MODE == 0) ? 512 : (MODE == 1) ? 1024
                    : (MODE == 2) ? 2048 : 512;
    constexpr int NSTEP = K / 32;

    extern __shared__ float smem[];
    float* AsBase = smem;            /* 4 * 4096 floats */
    float* BsBase = smem + 16384;    /* 4 * 4096 floats */

    int e = 0, cnt = NT, base = 0;
    if (MODE >= 2) {
        e = blockIdx.z;
        cnt = g_counts[e];
        base = g_offsets[e];
    }
    int m0 = blockIdx.y * 128;
    if (m0 >= cnt) return;
    int n0 = blockIdx.x * 128;

    const float* Wg = (MODE == 0) ? g_pint : (MODE == 1) ? g_poutt
                    : (MODE == 2) ? g_w1t : g_w2t;
    const float* Wp = Wg + (MODE >= 2 ? (size_t)e * K * N : 0);
    const float* bp = bias + (MODE >= 2 ? (size_t)e * N : 0);

    int tid = threadIdx.x;
    int wid = tid >> 5, lane = tid & 31;
    int wm = wid >> 2, wn = wid & 3;
    int g = lane >> 2, tq = lane & 3;

    /* A loader: 1024 16B-chunks / 256 thr = 4 each. row=(tid>>3)+32i, chunk=tid&7 */
    int acx = tid & 7;
    int arbase = tid >> 3;                       /* 0..31 */
    int ascol = ((acx ^ (arbase & 7)) << 2);
    const float* aptr[4];
#pragma unroll
    for (int i = 0; i < 4; i++) {
        int m = m0 + arbase + i * 32;
        const float* p = nullptr;
        if (m < cnt) {
            if (MODE == 0)      p = g_xfri + (size_t)m * K;
            else if (MODE == 1) p = g_moe + (size_t)m * K;
            else if (MODE == 2) p = g_h + (size_t)g_slot_token[base + m] * K;
            else                p = g_hid + (size_t)(base + m) * K;
        }
        aptr[i] = p;
    }
    /* B loader: 32 rows x 32 chunks / 256 thr = 4 each. row=(tid>>5)+8i */
    int bcx = tid & 31;
    int brbase = tid >> 5;                       /* 0..7 */
    int bscol = ((bcx ^ brbase) << 2);           /* brbase = row&7 for all i */

    uint32_t asb[4], bsb[4];
#pragma unroll
    for (int s = 0; s < 4; s++) {
        asb[s] = (uint32_t)__cvta_generic_to_shared(AsBase + s * 4096);
        bsb[s] = (uint32_t)__cvta_generic_to_shared(BsBase + s * 4096);
    }

    auto load_stage = [&](int st, int k0v) {
#pragma unroll
        for (int i = 0; i < 4; i++) {
            int r = arbase + i * 32;
            uint32_t dst = asb[st] + (uint32_t)((r * 32 + ascol) * 4);
            const float* src = aptr[i] ? (aptr[i] + k0v + acx * 4)
                                       : (const float*)g_moe;
            int sz = aptr[i] ? 16 : 0;
            asm volatile("cp.async.cg.shared.global [%0], [%1], 16, %2;"
                         :: "r"(dst), "l"(src), "r"(sz));
        }
#pragma unroll
        for (int i = 0; i < 4; i++) {
            int r = brbase + i * 8;
            uint32_t dst = bsb[st] + (uint32_t)((r * 128 + bscol) * 4);
            const float* src = Wp + (size_t)(k0v + r) * N + n0 + bcx * 4;
            asm volatile("cp.async.cg.shared.global [%0], [%1], 16;"
                         :: "r"(dst), "l"(src));
        }
    };

    float acc[4][4][4];
#pragma unroll
    for (int i = 0; i < 4; i++)
#pragma unroll
        for (int j = 0; j < 4; j++)
#pragma unroll
            for (int r = 0; r < 4; r++) acc[i][j][r] = 0.f;

    /* prologue: 3 stages in flight */
    load_stage(0, 0);
    asm volatile("cp.async.commit_group;");
    load_stage(1, 32);
    asm volatile("cp.async.commit_group;");
    load_stage(2, 64);
    asm volatile("cp.async.commit_group;");

    for (int it = 0; it < NSTEP; ++it) {
        if (it < NSTEP - 2)
            asm volatile("cp.async.wait_group 2;");
        else if (it == NSTEP - 2)
            asm volatile("cp.async.wait_group 1;");
        else
            asm volatile("cp.async.wait_group 0;");
        __syncthreads();

        if (it + 3 < NSTEP) {
            load_stage((it + 3) & 3, (it + 3) * 32);
            asm volatile("cp.async.commit_group;");
        }

        int cur = it & 3;
        float* Asc = AsBase + cur * 4096;
        float* Bsc = BsBase + cur * 4096;

#pragma unroll
        for (int kk = 0; kk < 32; kk += 8) {
            int c0 = kk >> 2;
            unsigned a[4][4];
#pragma unroll
            for (int i = 0; i < 4; i++) {
                int r0 = wm * 64 + i * 16 + g;
                int ca  = ((c0 ^ g) << 2) | tq;
                int ca4 = (((c0 + 1) ^ g) << 2) | tq;
                float v0 = Asc[r0 * 32 + ca];
                float v1 = Asc[(r0 + 8) * 32 + ca];
                float v2 = Asc[r0 * 32 + ca4];
                float v3 = Asc[(r0 + 8) * 32 + ca4];
                if (MODE == 0) {
                    a[i][0] = f2tf(v0); a[i][1] = f2tf(v1);
                    a[i][2] = f2tf(v2); a[i][3] = f2tf(v3);
                } else {
                    a[i][0] = __float_as_uint(v0); a[i][1] = __float_as_uint(v1);
                    a[i][2] = __float_as_uint(v2); a[i][3] = __float_as_uint(v3);
                }
            }
            unsigned b[4][2];
#pragma unroll
            for (int j = 0; j < 4; j++) {
                int cx = wn * 8 + j * 2 + (g >> 2);          /* 0..31 */
                int col0 = ((cx ^ tq) << 2) | (g & 3);
                int col1 = ((cx ^ (4 + tq)) << 2) | (g & 3);
                b[j][0] = __float_as_uint(Bsc[(kk + tq) * 128 + col0]);
                b[j][1] = __float_as_uint(Bsc[(kk + 4 + tq) * 128 + col1]);
            }
#pragma unroll
            for (int i = 0; i < 4; i++)
#pragma unroll
                for (int j = 0; j < 4; j++) mma_tf32(acc[i][j], a[i], b[j]);
        }
    }

    /* epilogue + writeback */
#pragma unroll
    for (int i = 0; i < 4; i++) {
        int r_lo = m0 + wm * 64 + i * 16 + g;
#pragma unroll
        for (int j = 0; j < 4; j++) {
            int n = n0 + wn * 32 + j * 8 + (tq << 1);
            float bn0 = bp[n], bn1 = bp[n + 1];
#pragma unroll
            for (int h = 0; h < 2; h++) {
                int m = r_lo + h * 8;
                if (m >= cnt) continue;
                float v0 = acc[i][j][h * 2 + 0] + bn0;
                float v1 = acc[i][j][h * 2 + 1] + bn1;
                if (MODE == 0) {
                    v0 = __uint_as_float(f2tf(v0));
                    v1 = __uint_as_float(f2tf(v1));
                    *(float2*)(g_h + (size_t)m * N + n) = make_float2(v0, v1);
                } else if (MODE == 2) {
                    v0 = 0.5f * v0 * (1.f + erff(v0 * 0.7071067811865475f));
                    v1 = 0.5f * v1 * (1.f + erff(v1 * 0.7071067811865475f));
                    v0 = __uint_as_float(f2tf(v0));
                    v1 = __uint_as_float(f2tf(v1));
                    *(float2*)(g_hid + (size_t)(base + m) * N + n) =
                        make_float2(v0, v1);
                } else if (MODE == 1) {
                    *(float2*)(g_of + (size_t)m * N + n) = make_float2(v0, v1);
                } else {
                    *(float2*)(g_eout + (size_t)(base + m) * N + n) =
                        make_float2(v0, v1);
                }
            }
        }
    }
}

/* ---------------- fused router: logits from exact g_xfri, top-2, hist ----- */
__global__ __launch_bounds__(256) void logits_topk_kernel() {
    __shared__ float Ws[8][1024];
    int tid = threadIdx.x;
    for (int i = tid; i < 8192; i += 256)
        Ws[i & 7][i >> 3] = g_wr[i];
    __syncthreads();

    int wid = tid >> 5, lane = tid & 31;
    int t = blockIdx.x * 8 + wid;
    if (t >= NT) return;

    const float4* xr = (const float4*)(g_xfri + (size_t)t * 1024);
    float acc[8] = {0.f, 0.f, 0.f, 0.f, 0.f, 0.f, 0.f, 0.f};
#pragma unroll
    for (int it = 0; it < 8; ++it) {
        float4 v = xr[it * 32 + lane];
        int k = it * 128 + lane * 4;
#pragma unroll
        for (int e = 0; e < 8; e++) {
            acc[e] += v.x * Ws[e][k]     + v.y * Ws[e][k + 1]
                    + v.z * Ws[e][k + 2] + v.w * Ws[e][k + 3];
        }
    }
#pragma unroll
    for (int e = 0; e < 8; e++)
        for (int o = 16; o; o >>= 1)
            acc[e] += __shfl_down_sync(0xffffffffu, acc[e], o);

    if (lane == 0) {
        float best = -1e30f, second = -1e30f;
        int bi = 0, si = 0;
#pragma unroll
        for (int e = 0; e < 8; e++) {
            float l = acc[e] + g_br[e];
            if (l > best)       { second = best; si = bi; best = l; bi = e; }
            else if (l > second){ second = l; si = e; }
        }
        float e1 = expf(second - best);
        float inv = 1.f / (1.f + e1);
        g_top_idx[2 * t]     = bi;
        g_top_idx[2 * t + 1] = si;
        g_top_w[2 * t]       = inv;
        g_top_w[2 * t + 1]   = e1 * inv;
        atomicAdd(&g_counts[bi], 1);
        atomicAdd(&g_counts[si], 1);
    }
}

__global__ void scan_kernel() {
    if (threadIdx.x == 0) {
        int off = 0;
        for (int e = 0; e < Em; e++) {
            g_offsets[e] = off;
            g_cursor[e]  = off;
            off += g_counts[e];
        }
    }
}

__global__ void scatter_kernel() {
    int t = blockIdx.x * blockDim.x + threadIdx.x;
    if (t < NT) {
        for (int k = 0; k < 2; k++) {
            int e = g_top_idx[2 * t + k];
            int slot = atomicAdd(&g_cursor[e], 1);
            g_slot_token[slot] = t;
            g_tok_slot[2 * t + k] = slot;
        }
    }
}

/* ---------------- combine top-2 expert outputs (deterministic) ------------ */
__global__ void combine_kernel() {
    int i = blockIdx.x * blockDim.x + threadIdx.x;
    if (i >= NT * Dm) return;
    int t = i >> 9, d = i & 511;
    int s0 = g_tok_slot[2 * t], s1 = g_tok_slot[2 * t + 1];
    float v = g_top_w[2 * t]     * g_eout[(size_t)s0 * Dm + d]
            + g_top_w[2 * t + 1] * g_eout[(size_t)s1 * Dm + d];
    g_moe[i] = __uint_as_float(f2tf(v));
}

/* ---------------- LayerNorm + residual ---------------- */
__global__ void ln_kernel(const float* __restrict__ x,
                          const float* __restrict__ gg,
                          const float* __restrict__ bb,
                          float* __restrict__ out) {
    int row = blockIdx.x;
    int tid = threadIdx.x;
    const float* v = g_ot + (size_t)row * Dm;

    float loc[4];
    float s = 0.f;
#pragma unroll
    for (int i = 0; i < 4; i++) {
        loc[i] = v[tid + i * 128];
        s += loc[i];
    }

    __shared__ float red[4];
    for (int o = 16; o; o >>= 1) s += __shfl_down_sync(0xffffffffu, s, o);
    if ((tid & 31) == 0) red[tid >> 5] = s;
    __syncthreads();
    float mu = (red[0] + red[1] + red[2] + red[3]) * (1.f / 512.f);
    __syncthreads();

    float q = 0.f;
#pragma unroll
    for (int i = 0; i < 4; i++) {
        float dd = loc[i] - mu;
        q += dd * dd;
    }
    for (int o = 16; o; o >>= 1) q += __shfl_down_sync(0xffffffffu, q, o);
    if ((tid & 31) == 0) red[tid >> 5] = q;
    __syncthreads();
    float var = (red[0] + red[1] + red[2] + red[3]) * (1.f / 512.f);
    float rs = rsqrtf(var + 1e-5f);

#pragma unroll
    for (int i = 0; i < 4; i++) {
        int d = tid + i * 128;
        size_t o = (size_t)row * Dm + d;
        out[o] = (loc[i] - mu) * rs * gg[d] + bb[d] + x[o];
    }
}

/* ---------------- launch ---------------- */
extern "C" void kernel_launch(void* const* d_in, const int* in_sizes, int n_in,
                              void* d_out, int out_size) {
    const float* x        = (const float*)d_in[0];
    const float* pin_w    = (const float*)d_in[1];
    const float* pin_b    = (const float*)d_in[2];
    const float* router_w = (const float*)d_in[3];
    const float* router_b = (const float*)d_in[4];
    const float* w1       = (const float*)d_in[5];
    const float* b1       = (const float*)d_in[6];
    const float* w2       = (const float*)d_in[7];
    const float* b2       = (const float*)d_in[8];
    const float* pout_w   = (const float*)d_in[9];
    const float* pout_b   = (const float*)d_in[10];
    const float* ln_g     = (const float*)d_in[11];
    const float* ln_b     = (const float*)d_in[12];
    float* out = (float*)d_out;

    const int MB = (NT + 127) / 128;   /* 129 M-tiles for tf32 kernels */
    const int GSM = 131072;            /* 128KB dynamic smem: 4-stage pipe */

    cudaFuncSetAttribute(gemm_tf32_kernel<0>,
                         cudaFuncAttributeMaxDynamicSharedMemorySize, GSM);
    cudaFuncSetAttribute(gemm_tf32_kernel<1>,
                         cudaFuncAttributeMaxDynamicSharedMemorySize, GSM);
    cudaFuncSetAttribute(gemm_tf32_kernel<2>,
                         cudaFuncAttributeMaxDynamicSharedMemorySize, GSM);
    cudaFuncSetAttribute(gemm_tf32_kernel<3>,
                         cudaFuncAttributeMaxDynamicSharedMemorySize, GSM);

    setup_kernel<<<16, 256>>>();
    preround_kernel<<<32768, 256>>>(w1, w2, pout_w, pin_w);
    wr_kernel<<<1025, 128>>>(pin_w, pin_b, router_w, router_b);
    fft_fwd_kernel<<<Bn * 256, 256>>>(x);
    gemm_tf32_kernel<0><<<dim3(512 / 128, MB), 256, GSM>>>(pin_b);
    logits_topk_kernel<<<(NT + 7) / 8, 256>>>();
    scan_kernel<<<1, 1>>>();
    scatter_kernel<<<(NT + 255) / 256, 256>>>();
    gemm_tf32_kernel<2><<<dim3(DFF / 128, MB, Em), 256, GSM>>>(b1);
    gemm_tf32_kernel<3><<<dim3(Dm / 128, MB, Em), 256, GSM>>>(b2);
    combine_kernel<<<(NT * Dm + 255) / 256, 256>>>();
    gemm_tf32_kernel<1><<<dim3(1024 / 128, MB), 256, GSM>>>(pout_b);
    fft_inv_kernel<<<Bn * 256, 256>>>();
    ln_kernel<<<Bn * Sn, 128>>>(x, ln_g, ln_b, out);
}

// round 14
// speedup vs baseline: 1.1648x; 1.1648x over previous
#include <cuda_runtime.h>
#include <cstdint>

#define Bn   8
#define Sn   4096
#define Dm   512
#define Fn   2049
#define Em   8
#define DFF  2048
#define NT   (Bn * Fn)      /* 16392 tokens in frequency domain */
#define NSLOT (2 * NT)      /* 32784 token-expert slots */

/* ---------------- scratch (device globals; no runtime alloc allowed) -------- */
__device__ float g_xfri[16785408];   /* NT x 1024  (re | im), EXACT fp32 */
__device__ float g_h   [8392704];    /* NT x 512  (tf32-rounded at pin epi) */
__device__ float g_moe [8392704];    /* NT x 512  (tf32-rounded at combine) */
__device__ float g_of  [16785408];   /* NT x 1024 */
__device__ float g_ot  [16777216];   /* B x S x D */
__device__ float g_hid [67141632];   /* NSLOT x 2048 (tf32-rounded at store) */
__device__ float g_eout[16785408];   /* NSLOT x 512 */
__device__ float g_w1t [8388608];    /* tf32-rounded w1 */
__device__ float g_w2t [8388608];    /* tf32-rounded w2 */
__device__ float g_poutt[524288];    /* tf32-rounded pout_w */
__device__ float g_pint [524288];    /* tf32-rounded pin_w */
__device__ float g_wr  [8192];       /* fused router weights pin_w @ router_w */
__device__ float g_br  [8];          /* fused router bias */
__device__ float2 g_tw [4096];       /* twiddle table: index = half + pos */
__device__ int   g_top_idx[NT * 2];
__device__ float g_top_w [NT * 2];
__device__ int   g_counts[Em];
__device__ int   g_offsets[Em];
__device__ int   g_cursor[Em];
__device__ int   g_slot_token[NSLOT];
__device__ int   g_tok_slot[NT * 2];

__device__ __forceinline__ unsigned f2tf(float f) {
    unsigned u;
    asm("cvt.rna.tf32.f32 %0, %1;" : "=r"(u) : "f"(f));
    return u;
}

/* ---------------- setup: zero counts + build twiddle table ---------------- */
__global__ void setup_kernel() {
    int i = blockIdx.x * blockDim.x + threadIdx.x;
    if (i < Em) g_counts[i] = 0;
    if (i >= 1 && i < 4096) {
        int half = 1 << (31 - __clz(i));
        int pos  = i - half;
        float ang = -6.283185307179586f * (float)pos / (float)(2 * half);
        float sn, cs;
        sincosf(ang, &sn, &cs);
        g_tw[i] = make_float2(cs, sn);
    }
}

/* ---------------- pre-round weights to tf32 (once per launch) ------------- */
__global__ void preround_kernel(const float* __restrict__ w1,
                                const float* __restrict__ w2,
                                const float* __restrict__ pw,
                                const float* __restrict__ piw) {
    int i = blockIdx.x * blockDim.x + threadIdx.x;
    if (i < 8388608) {
        g_w1t[i] = __uint_as_float(f2tf(w1[i]));
        g_w2t[i] = __uint_as_float(f2tf(w2[i]));
    }
    if (i < 524288) {
        g_poutt[i] = __uint_as_float(f2tf(pw[i]));
        g_pint[i]  = __uint_as_float(f2tf(piw[i]));
    }
}

/* ---------------- fused router weights: Wr = pin_w @ router_w ------------- */
__global__ void wr_kernel(const float* __restrict__ pin_w,
                          const float* __restrict__ pin_b,
                          const float* __restrict__ rw,
                          const float* __restrict__ rb) {
    int f = blockIdx.x, tid = threadIdx.x;
    if (f == 1024) {
        if (tid < 8) {
            float s = rb[tid];
            for (int d = 0; d < 512; d++) s += pin_b[d] * rw[d * 8 + tid];
            g_br[tid] = s;
        }
        return;
    }
    float acc[8] = {0.f, 0.f, 0.f, 0.f, 0.f, 0.f, 0.f, 0.f};
    for (int d = tid; d < 512; d += 128) {
        float pv = pin_w[f * 512 + d];
        const float* r = rw + d * 8;
#pragma unroll
        for (int e = 0; e < 8; e++) acc[e] += pv * r[e];
    }
    __shared__ float red[4][8];
#pragma unroll
    for (int e = 0; e < 8; e++)
        for (int o = 16; o; o >>= 1)
            acc[e] += __shfl_down_sync(0xffffffffu, acc[e], o);
    if ((tid & 31) == 0) {
#pragma unroll
        for (int e = 0; e < 8; e++) red[tid >> 5][e] = acc[e];
    }
    __syncthreads();
    if (tid < 8)
        g_wr[f * 8 + tid] = red[0][tid] + red[1][tid] + red[2][tid] + red[3][tid];
}

/* skewed smem index: kills 2-way bank conflicts in butterfly stages */
#define IX(i) ((i) + ((i) >> 5))

/* base-4 digit reversal of a 12-bit index */
__device__ __forceinline__ unsigned dr4(unsigned s) {
    unsigned t = __brev(s) >> 20;
    return ((t & 0x555u) << 1) | ((t >> 1) & 0x555u);
}

template <int INV, int S>
__device__ __forceinline__ void bfly4(float* xr, float* xi,
                                      float2 w1, float2 w2) {
    float w1i = INV ? -w1.y : w1.y;
    float w2i = INV ? -w2.y : w2.y;
    float w3r = w1.x * w2.x - w1i * w2i;
    float w3i = w1.x * w2i + w1i * w2.x;
    float t0r = xr[0], t0i = xi[0];
    float t1r = xr[S] * w1.x - xi[S] * w1i;
    float t1i = xr[S] * w1i + xi[S] * w1.x;
    float t2r = xr[2 * S] * w2.x - xi[2 * S] * w2i;
    float t2i = xr[2 * S] * w2i + xi[2 * S] * w2.x;
    float t3r = xr[3 * S] * w3r - xi[3 * S] * w3i;
    float t3i = xr[3 * S] * w3i + xi[3 * S] * w3r;
    float s0r = t0r + t2r, s0i = t0i + t2i;
    float s1r = t0r - t2r, s1i = t0i - t2i;
    float s2r = t1r + t3r, s2i = t1i + t3i;
    float s3r = t1r - t3r, s3i = t1i - t3i;
    xr[0] = s0r + s2r;     xi[0] = s0i + s2i;
    xr[2 * S] = s0r - s2r; xi[2 * S] = s0i - s2i;
    if (!INV) {
        xr[S] = s1r + s3i;     xi[S] = s1i - s3r;
        xr[3 * S] = s1r - s3i; xi[3 * S] = s1i + s3r;
    } else {
        xr[S] = s1r - s3i;     xi[S] = s1i + s3r;
        xr[3 * S] = s1r + s3i; xi[3 * S] = s1i - s3r;
    }
}

template <int INV>
__device__ __forceinline__ void pair16(float* xr, float* xi, int Q, int pos) {
    float2 wA1 = g_tw[2 * Q + pos];
    float2 wA2 = g_tw[Q + pos];
#pragma unroll
    for (int b = 0; b < 4; b++)
        bfly4<INV, 1>(xr + 4 * b, xi + 4 * b, wA1, wA2);
#pragma unroll
    for (int c = 0; c < 4; c++) {
        float2 wB1 = g_tw[8 * Q + pos + c * Q];
        float2 wB2 = g_tw[4 * Q + pos + c * Q];
        bfly4<INV, 4>(xr + c, xi + c, wB1, wB2);
    }
}

/* ---------------- forward rfft, two d-columns per block (two-for-one) ------ */
__global__ __launch_bounds__(256) void fft_fwd_kernel(const float* __restrict__ x) {
    __shared__ float re[4224];
    __shared__ float im[4224];
    int pr = blockIdx.x;
    int b = pr >> 8, d0 = (pr & 255) << 1;
    int tid = threadIdx.x;

    float xr[16], xi[16];

#pragma unroll
    for (int k = 0; k < 16; k++) {
        unsigned s = dr4((unsigned)(16 * tid + k));
        float2 v = *(const float2*)(x + ((size_t)b * Sn + s) * Dm + d0);
        xr[k] = v.x;
        xi[k] = v.y;
    }
    pair16<0>(xr, xi, 1, 0);
#pragma unroll
    for (int k = 0; k < 16; k++) {
        int i = 16 * tid + k;
        re[IX(i)] = xr[k];
        im[IX(i)] = xi[k];
    }
    __syncthreads();

    {
        int pos = tid & 15, g = ((tid >> 4) << 8) + pos;
#pragma unroll
        for (int k = 0; k < 16; k++) {
            int i = g + (k << 4);
            xr[k] = re[IX(i)];
            xi[k] = im[IX(i)];
        }
        pair16<0>(xr, xi, 16, pos);
#pragma unroll
        for (int k = 0; k < 16; k++) {
            int i = g + (k << 4);
            re[IX(i)] = xr[k];
            im[IX(i)] = xi[k];
        }
    }
    __syncthreads();

    {
#pragma unroll
        for (int k = 0; k < 16; k++) {
            int i = tid + (k << 8);
            xr[k] = re[IX(i)];
            xi[k] = im[IX(i)];
        }
        pair16<0>(xr, xi, 256, tid);
#pragma unroll
        for (int k = 0; k < 16; k++) {
            int i = tid + (k << 8);
            re[IX(i)] = xr[k];
            im[IX(i)] = xi[k];
        }
    }
    __syncthreads();

    const float sc = 0.5f * 0.015625f;   /* 0.5 (split) * 1/sqrt(4096) */
    for (int k = tid; k <= 2048; k += 256) {
        int k2 = (4096 - k) & 4095;
        float zr  = re[IX(k)],  zi  = im[IX(k)];
        float z2r = re[IX(k2)], z2i = im[IX(k2)];
        float xdr = (zr + z2r) * sc, xdi = (zi - z2i) * sc;
        float xer = (zi + z2i) * sc, xei = (z2r - zr) * sc;
        size_t o = ((size_t)b * Fn + k) * 1024 + d0;
        *(float2*)(g_xfri + o)       = make_float2(xdr, xer);
        *(float2*)(g_xfri + o + 512) = make_float2(xdi, xei);
    }
}

/* ---------------- inverse rfft, two d-columns per block -------------------- */
__global__ __launch_bounds__(256) void fft_inv_kernel() {
    __shared__ float re[4224];
    __shared__ float im[4224];
    int pr = blockIdx.x;
    int b = pr >> 8, d0 = (pr & 255) << 1;
    int tid = threadIdx.x;

    float xr[16], xi[16];

#pragma unroll
    for (int k = 0; k < 16; k++) {
        unsigned ks = dr4((unsigned)(16 * tid + k));
        float zr, zi;
        if (ks <= 2048) {
            size_t o = ((size_t)b * Fn + ks) * 1024 + d0;
            float2 vre = *(const float2*)(g_of + o);
            float2 vim = *(const float2*)(g_of + o + 512);
            float a = vre.x, c = vre.y, bb = vim.x, dd = vim.y;
            if (ks == 0 || ks == 2048) { bb = 0.f; dd = 0.f; }
            zr = a - dd;
            zi = bb + c;
        } else {
            int k2 = 4096 - (int)ks;
            size_t o = ((size_t)b * Fn + k2) * 1024 + d0;
            float2 vre = *(const float2*)(g_of + o);
            float2 vim = *(const float2*)(g_of + o + 512);
            float a = vre.x, c = vre.y, bb = vim.x, dd = vim.y;
            zr = a + dd;
            zi = c - bb;
        }
        xr[k] = zr;
        xi[k] = zi;
    }
    pair16<1>(xr, xi, 1, 0);
#pragma unroll
    for (int k = 0; k < 16; k++) {
        int i = 16 * tid + k;
        re[IX(i)] = xr[k];
        im[IX(i)] = xi[k];
    }
    __syncthreads();

    {
        int pos = tid & 15, g = ((tid >> 4) << 8) + pos;
#pragma unroll
        for (int k = 0; k < 16; k++) {
            int i = g + (k << 4);
            xr[k] = re[IX(i)];
            xi[k] = im[IX(i)];
        }
        pair16<1>(xr, xi, 16, pos);
#pragma unroll
        for (int k = 0; k < 16; k++) {
            int i = g + (k << 4);
            re[IX(i)] = xr[k];
            im[IX(i)] = xi[k];
        }
    }
    __syncthreads();

    {
#pragma unroll
        for (int k = 0; k < 16; k++) {
            int i = tid + (k << 8);
            xr[k] = re[IX(i)];
            xi[k] = im[IX(i)];
        }
        pair16<1>(xr, xi, 256, tid);
        const float sc = 0.015625f;
#pragma unroll
        for (int k = 0; k < 16; k++) {
            int s = tid + (k << 8);
            *(float2*)(g_ot + ((size_t)b * Sn + s) * Dm + d0) =
                make_float2(xr[k] * sc, xi[k] * sc);
        }
    }
}

/* ==================== pipelined tf32 tensor-core GEMM ====================
   Block tile 128(M) x 128(N) x 32(K), 256 threads = 8 warps (2x4).
   Warp tile 64x32 = 4x4 grid of mma.sync.m16n8k8 tf32 tiles.
   3-stage cp.async pipeline (96KB dynamic smem -> 2 CTAs/SM), ONE
   __syncthreads per K-iteration: load target (it+2)%3 was last read at
   iteration it-1, so the top-of-loop barrier alone orders reuse.
   MODE 0: g_h   = cvt(g_xfri) @ g_pint + pin_b          (K=1024, N=512)
   MODE 1: g_of  = g_moe  @ g_poutt + pout_b             (K=512,  N=1024)
   MODE 2: g_hid = gelu(gather(g_h) @ g_w1t + b1[e])     (K=512,  N=2048)
   MODE 3: g_eout= g_hid @ g_w2t + b2[e]                 (K=2048, N=512)  */

__device__ __forceinline__ void mma_tf32(float c[4], const unsigned a[4],
                                         const unsigned b[2]) {
    asm volatile(
        "mma.sync.aligned.m16n8k8.row.col.f32.tf32.tf32.f32 "
        "{%0,%1,%2,%3}, {%4,%5,%6,%7}, {%8,%9}, {%0,%1,%2,%3};\n"
        : "+f"(c[0]), "+f"(c[1]), "+f"(c[2]), "+f"(c[3])
        : "r"(a[0]), "r"(a[1]), "r"(a[2]), "r"(a[3]), "r"(b[0]), "r"(b[1]));
}

/* dynamic smem layout (floats):
   As[3][128][32] at 0      (stage s at s*4096)
   Bs[3][32][128] at 12288  (stage s at 12288 + s*4096)                    */
template <int MODE>
__global__ __launch_bounds__(256, 2) void gemm_tf32_kernel(
        const float* __restrict__ bias) {
    constexpr int K = (MODE == 0) ? 1024 : (MODE == 3) ? 2048 : 512;
    constexpr int N = (MODE == 0) ? 512 : (MODE == 1) ? 1024
                    : (MODE == 2) ? 2048 : 512;
    constexpr int NSTEP = K / 32;

    extern __shared__ float smem[];
    float* AsBase = smem;            /* 3 * 4096 floats */
    float* BsBase = smem + 12288;    /* 3 * 4096 floats */

    int e = 0, cnt = NT, base = 0;
    if (MODE >= 2) {
        e = blockIdx.z;
        cnt = g_counts[e];
        base = g_offsets[e];
    }
    int m0 = blockIdx.y * 128;
    if (m0 >= cnt) return;
    int n0 = blockIdx.x * 128;

    const float* Wg = (MODE == 0) ? g_pint : (MODE == 1) ? g_poutt
                    : (MODE == 2) ? g_w1t : g_w2t;
    const float* Wp = Wg + (MODE >= 2 ? (size_t)e * K * N : 0);
    const float* bp = bias + (MODE >= 2 ? (size_t)e * N : 0);

    int tid = threadIdx.x;
    int wid = tid >> 5, lane = tid & 31;
    int wm = wid >> 2, wn = wid & 3;
    int g = lane >> 2, tq = lane & 3;

    /* A loader: 1024 16B-chunks / 256 thr = 4 each. row=(tid>>3)+32i, chunk=tid&7 */
    int acx = tid & 7;
    int arbase = tid >> 3;                       /* 0..31 */
    int ascol = ((acx ^ (arbase & 7)) << 2);
    const float* aptr[4];
#pragma unroll
    for (int i = 0; i < 4; i++) {
        int m = m0 + arbase + i * 32;
        const float* p = nullptr;
        if (m < cnt) {
            if (MODE == 0)      p = g_xfri + (size_t)m * K;
            else if (MODE == 1) p = g_moe + (size_t)m * K;
            else if (MODE == 2) p = g_h + (size_t)g_slot_token[base + m] * K;
            else                p = g_hid + (size_t)(base + m) * K;
        }
        aptr[i] = p;
    }
    /* B loader: 32 rows x 32 chunks / 256 thr = 4 each. row=(tid>>5)+8i */
    int bcx = tid & 31;
    int brbase = tid >> 5;                       /* 0..7 */
    int bscol = ((bcx ^ brbase) << 2);           /* brbase = row&7 for all i */

    uint32_t asb[3], bsb[3];
#pragma unroll
    for (int s = 0; s < 3; s++) {
        asb[s] = (uint32_t)__cvta_generic_to_shared(AsBase + s * 4096);
        bsb[s] = (uint32_t)__cvta_generic_to_shared(BsBase + s * 4096);
    }

    auto load_stage = [&](int st, int k0v) {
#pragma unroll
        for (int i = 0; i < 4; i++) {
            int r = arbase + i * 32;
            uint32_t dst = asb[st] + (uint32_t)((r * 32 + ascol) * 4);
            const float* src = aptr[i] ? (aptr[i] + k0v + acx * 4)
                                       : (const float*)g_moe;
            int sz = aptr[i] ? 16 : 0;
            asm volatile("cp.async.cg.shared.global [%0], [%1], 16, %2;"
                         :: "r"(dst), "l"(src), "r"(sz));
        }
#pragma unroll
        for (int i = 0; i < 4; i++) {
            int r = brbase + i * 8;
            uint32_t dst = bsb[st] + (uint32_t)((r * 128 + bscol) * 4);
            const float* src = Wp + (size_t)(k0v + r) * N + n0 + bcx * 4;
            asm volatile("cp.async.cg.shared.global [%0], [%1], 16;"
                         :: "r"(dst), "l"(src));
        }
    };

    float acc[4][4][4];
#pragma unroll
    for (int i = 0; i < 4; i++)
#pragma unroll
        for (int j = 0; j < 4; j++)
#pragma unroll
            for (int r = 0; r < 4; r++) acc[i][j][r] = 0.f;

    /* prologue: 2 stages in flight */
    load_stage(0, 0);
    asm volatile("cp.async.commit_group;");
    load_stage(1, 32);
    asm volatile("cp.async.commit_group;");

    int cur = 0;
    for (int it = 0; it < NSTEP; ++it) {
        if (it < NSTEP - 1)
            asm volatile("cp.async.wait_group 1;");
        else
            asm volatile("cp.async.wait_group 0;");
        __syncthreads();

        if (it + 2 < NSTEP) {
            int nb = cur + 2; if (nb >= 3) nb -= 3;
            load_stage(nb, (it + 2) * 32);
            asm volatile("cp.async.commit_group;");
        }

        float* Asc = AsBase + cur * 4096;
        float* Bsc = BsBase + cur * 4096;

#pragma unroll
        for (int kk = 0; kk < 32; kk += 8) {
            int c0 = kk >> 2;
            unsigned a[4][4];
#pragma unroll
            for (int i = 0; i < 4; i++) {
                int r0 = wm * 64 + i * 16 + g;
                int ca  = ((c0 ^ g) << 2) | tq;
                int ca4 = (((c0 + 1) ^ g) << 2) | tq;
                float v0 = Asc[r0 * 32 + ca];
                float v1 = Asc[(r0 + 8) * 32 + ca];
                float v2 = Asc[r0 * 32 + ca4];
                float v3 = Asc[(r0 + 8) * 32 + ca4];
                if (MODE == 0) {
                    a[i][0] = f2tf(v0); a[i][1] = f2tf(v1);
                    a[i][2] = f2tf(v2); a[i][3] = f2tf(v3);
                } else {
                    a[i][0] = __float_as_uint(v0); a[i][1] = __float_as_uint(v1);
                    a[i][2] = __float_as_uint(v2); a[i][3] = __float_as_uint(v3);
                }
            }
            unsigned b[4][2];
#pragma unroll
            for (int j = 0; j < 4; j++) {
                int cx = wn * 8 + j * 2 + (g >> 2);          /* 0..31 */
                int col0 = ((cx ^ tq) << 2) | (g & 3);
                int col1 = ((cx ^ (4 + tq)) << 2) | (g & 3);
                b[j][0] = __float_as_uint(Bsc[(kk + tq) * 128 + col0]);
                b[j][1] = __float_as_uint(Bsc[(kk + 4 + tq) * 128 + col1]);
            }
#pragma unroll
            for (int i = 0; i < 4; i++)
#pragma unroll
                for (int j = 0; j < 4; j++) mma_tf32(acc[i][j], a[i], b[j]);
        }

        if (++cur == 3) cur = 0;
    }

    /* epilogue + writeback */
#pragma unroll
    for (int i = 0; i < 4; i++) {
        int r_lo = m0 + wm * 64 + i * 16 + g;
#pragma unroll
        for (int j = 0; j < 4; j++) {
            int n = n0 + wn * 32 + j * 8 + (tq << 1);
            float bn0 = bp[n], bn1 = bp[n + 1];
#pragma unroll
            for (int h = 0; h < 2; h++) {
                int m = r_lo + h * 8;
                if (m >= cnt) continue;
                float v0 = acc[i][j][h * 2 + 0] + bn0;
                float v1 = acc[i][j][h * 2 + 1] + bn1;
                if (MODE == 0) {
                    v0 = __uint_as_float(f2tf(v0));
                    v1 = __uint_as_float(f2tf(v1));
                    *(float2*)(g_h + (size_t)m * N + n) = make_float2(v0, v1);
                } else if (MODE == 2) {
                    v0 = 0.5f * v0 * (1.f + erff(v0 * 0.7071067811865475f));
                    v1 = 0.5f * v1 * (1.f + erff(v1 * 0.7071067811865475f));
                    v0 = __uint_as_float(f2tf(v0));
                    v1 = __uint_as_float(f2tf(v1));
                    *(float2*)(g_hid + (size_t)(base + m) * N + n) =
                        make_float2(v0, v1);
                } else if (MODE == 1) {
                    *(float2*)(g_of + (size_t)m * N + n) = make_float2(v0, v1);
                } else {
                    *(float2*)(g_eout + (size_t)(base + m) * N + n) =
                        make_float2(v0, v1);
                }
            }
        }
    }
}

/* ---------------- fused router: logits from exact g_xfri, top-2, hist ----- */
__global__ __launch_bounds__(256) void logits_topk_kernel() {
    __shared__ float Ws[8][1024];
    int tid = threadIdx.x;
    for (int i = tid; i < 8192; i += 256)
        Ws[i & 7][i >> 3] = g_wr[i];
    __syncthreads();

    int wid = tid >> 5, lane = tid & 31;
    int t = blockIdx.x * 8 + wid;
    if (t >= NT) return;

    const float4* xr = (const float4*)(g_xfri + (size_t)t * 1024);
    float acc[8] = {0.f, 0.f, 0.f, 0.f, 0.f, 0.f, 0.f, 0.f};
#pragma unroll
    for (int it = 0; it < 8; ++it) {
        float4 v = xr[it * 32 + lane];
        int k = it * 128 + lane * 4;
#pragma unroll
        for (int e = 0; e < 8; e++) {
            acc[e] += v.x * Ws[e][k]     + v.y * Ws[e][k + 1]
                    + v.z * Ws[e][k + 2] + v.w * Ws[e][k + 3];
        }
    }
#pragma unroll
    for (int e = 0; e < 8; e++)
        for (int o = 16; o; o >>= 1)
            acc[e] += __shfl_down_sync(0xffffffffu, acc[e], o);

    if (lane == 0) {
        float best = -1e30f, second = -1e30f;
        int bi = 0, si = 0;
#pragma unroll
        for (int e = 0; e < 8; e++) {
            float l = acc[e] + g_br[e];
            if (l > best)       { second = best; si = bi; best = l; bi = e; }
            else if (l > second){ second = l; si = e; }
        }
        float e1 = expf(second - best);
        float inv = 1.f / (1.f + e1);
        g_top_idx[2 * t]     = bi;
        g_top_idx[2 * t + 1] = si;
        g_top_w[2 * t]       = inv;
        g_top_w[2 * t + 1]   = e1 * inv;
        atomicAdd(&g_counts[bi], 1);
        atomicAdd(&g_counts[si], 1);
    }
}

__global__ void scan_kernel() {
    if (threadIdx.x == 0) {
        int off = 0;
        for (int e = 0; e < Em; e++) {
            g_offsets[e] = off;
            g_cursor[e]  = off;
            off += g_counts[e];
        }
    }
}

__global__ void scatter_kernel() {
    int t = blockIdx.x * blockDim.x + threadIdx.x;
    if (t < NT) {
        for (int k = 0; k < 2; k++) {
            int e = g_top_idx[2 * t + k];
            int slot = atomicAdd(&g_cursor[e], 1);
            g_slot_token[slot] = t;
            g_tok_slot[2 * t + k] = slot;
        }
    }
}

/* ---------------- combine top-2 expert outputs (deterministic) ------------ */
__global__ void combine_kernel() {
    int i = blockIdx.x * blockDim.x + threadIdx.x;
    if (i >= NT * Dm) return;
    int t = i >> 9, d = i & 511;
    int s0 = g_tok_slot[2 * t], s1 = g_tok_slot[2 * t + 1];
    float v = g_top_w[2 * t]     * g_eout[(size_t)s0 * Dm + d]
            + g_top_w[2 * t + 1] * g_eout[(size_t)s1 * Dm + d];
    g_moe[i] = __uint_as_float(f2tf(v));
}

/* ---------------- LayerNorm + residual ---------------- */
__global__ void ln_kernel(const float* __restrict__ x,
                          const float* __restrict__ gg,
                          const float* __restrict__ bb,
                          float* __restrict__ out) {
    int row = blockIdx.x;
    int tid = threadIdx.x;
    const float* v = g_ot + (size_t)row * Dm;

    float loc[4];
    float s = 0.f;
#pragma unroll
    for (int i = 0; i < 4; i++) {
        loc[i] = v[tid + i * 128];
        s += loc[i];
    }

    __shared__ float red[4];
    for (int o = 16; o; o >>= 1) s += __shfl_down_sync(0xffffffffu, s, o);
    if ((tid & 31) == 0) red[tid >> 5] = s;
    __syncthreads();
    float mu = (red[0] + red[1] + red[2] + red[3]) * (1.f / 512.f);
    __syncthreads();

    float q = 0.f;
#pragma unroll
    for (int i = 0; i < 4; i++) {
        float dd = loc[i] - mu;
        q += dd * dd;
    }
    for (int o = 16; o; o >>= 1) q += __shfl_down_sync(0xffffffffu, q, o);
    if ((tid & 31) == 0) red[tid >> 5] = q;
    __syncthreads();
    float var = (red[0] + red[1] + red[2] + red[3]) * (1.f / 512.f);
    float rs = rsqrtf(var + 1e-5f);

#pragma unroll
    for (int i = 0; i < 4; i++) {
        int d = tid + i * 128;
        size_t o = (size_t)row * Dm + d;
        out[o] = (loc[i] - mu) * rs * gg[d] + bb[d] + x[o];
    }
}

/* ---------------- launch ---------------- */
extern "C" void kernel_launch(void* const* d_in, const int* in_sizes, int n_in,
                              void* d_out, int out_size) {
    const float* x        = (const float*)d_in[0];
    const float* pin_w    = (const float*)d_in[1];
    const float* pin_b    = (const float*)d_in[2];
    const float* router_w = (const float*)d_in[3];
    const float* router_b = (const float*)d_in[4];
    const float* w1       = (const float*)d_in[5];
    const float* b1       = (const float*)d_in[6];
    const float* w2       = (const float*)d_in[7];
    const float* b2       = (const float*)d_in[8];
    const float* pout_w   = (const float*)d_in[9];
    const float* pout_b   = (const float*)d_in[10];
    const float* ln_g     = (const float*)d_in[11];
    const float* ln_b     = (const float*)d_in[12];
    float* out = (float*)d_out;

    const int MB = (NT + 127) / 128;   /* 129 M-tiles for tf32 kernels */
    const int GSM = 98304;             /* 96KB dynamic smem: 3-stage pipe */

    cudaFuncSetAttribute(gemm_tf32_kernel<0>,
                         cudaFuncAttributeMaxDynamicSharedMemorySize, GSM);
    cudaFuncSetAttribute(gemm_tf32_kernel<1>,
                         cudaFuncAttributeMaxDynamicSharedMemorySize, GSM);
    cudaFuncSetAttribute(gemm_tf32_kernel<2>,
                         cudaFuncAttributeMaxDynamicSharedMemorySize, GSM);
    cudaFuncSetAttribute(gemm_tf32_kernel<3>,
                         cudaFuncAttributeMaxDynamicSharedMemorySize, GSM);

    setup_kernel<<<16, 256>>>();
    preround_kernel<<<32768, 256>>>(w1, w2, pout_w, pin_w);
    wr_kernel<<<1025, 128>>>(pin_w, pin_b, router_w, router_b);
    fft_fwd_kernel<<<Bn * 256, 256>>>(x);
    gemm_tf32_kernel<0><<<dim3(512 / 128, MB), 256, GSM>>>(pin_b);
    logits_topk_kernel<<<(NT + 7) / 8, 256>>>();
    scan_kernel<<<1, 1>>>();
    scatter_kernel<<<(NT + 255) / 256, 256>>>();
    gemm_tf32_kernel<2><<<dim3(DFF / 128, MB, Em), 256, GSM>>>(b1);
    gemm_tf32_kernel<3><<<dim3(Dm / 128, MB, Em), 256, GSM>>>(b2);
    combine_kernel<<<(NT * Dm + 255) / 256, 256>>>();
    gemm_tf32_kernel<1><<<dim3(1024 / 128, MB), 256, GSM>>>(pout_b);
    fft_inv_kernel<<<Bn * 256, 256>>>();
    ln_kernel<<<Bn * Sn, 128>>>(x, ln_g, ln_b, out);
}